// round 15
// baseline (speedup 1.0000x reference)
#include <cuda_runtime.h>
#include <cuda_fp16.h>
#include <math.h>
#include <cstdint>

typedef unsigned long long ull;

// ---------------- problem constants ----------------
#define BATCH 8
#define HWP   65536
#define G2    128
#define DD    9

// smem row stride in bytes (multiple of 16 for ldmatrix/float4)
#define RS 80

// ---------------- scratch ----------------------------------------------------
__device__ __align__(16) float d_xemb[BATCH * 64 * HWP];
__device__ __align__(16) float d_yemb[BATCH * 64 * HWP];
__device__ __align__(16) float d_h   [BATCH * G2 * HWP];
__device__ __align__(16) float d_gates[BATCH * DD * HWP];
__device__ __align__(16) float d_r0  [BATCH * HWP];
__device__ __align__(16) float d_r1  [BATCH * HWP];
__device__ __align__(16) __half d_W1h[72 * 4096];   // [ch][co][kk] fp16

// ---------------- helpers ----------------------------------------------------
__device__ __forceinline__ uint32_t smem_u32(const void* p) {
    uint32_t a;
    asm("{ .reg .u64 t; cvta.to.shared.u64 t, %1; cvt.u32.u64 %0, t; }" : "=r"(a) : "l"(p));
    return a;
}
__device__ __forceinline__ ull ffma2(ull a, ull b, ull c) {
    ull d; asm("fma.rn.f32x2 %0, %1, %2, %3;" : "=l"(d) : "l"(a), "l"(b), "l"(c)); return d;
}
__device__ __forceinline__ ull pack2(float a) {
    ull d; asm("mov.b64 %0, {%1, %1};" : "=l"(d) : "f"(a)); return d;
}
__device__ __forceinline__ void ldsm_x4(uint32_t* r, uint32_t addr) {
    asm volatile("ldmatrix.sync.aligned.m8n8.x4.shared.b16 {%0,%1,%2,%3}, [%4];"
                 : "=r"(r[0]), "=r"(r[1]), "=r"(r[2]), "=r"(r[3]) : "r"(addr));
}
__device__ __forceinline__ void mma_f16(float* d,
                                        const uint32_t* a, uint32_t b0, uint32_t b1) {
    asm volatile("mma.sync.aligned.m16n8k16.row.col.f32.f16.f16.f32 "
                 "{%0,%1,%2,%3}, {%4,%5,%6,%7}, {%8,%9}, {%0,%1,%2,%3};"
                 : "+f"(d[0]), "+f"(d[1]), "+f"(d[2]), "+f"(d[3])
                 : "r"(a[0]), "r"(a[1]), "r"(a[2]), "r"(a[3]), "r"(b0), "r"(b1));
}

// ---------------- 0: Wg1 -> fp16 tiles [ch][co][kk] -------------------------
// k = ch*32+kk ; tap = ch>>3 ; ci256 = (ch&7)*32 + kk
__global__ void prep_w1(const float* __restrict__ Wg1) {
    int i = blockIdx.x * 256 + threadIdx.x;
    if (i >= 72 * 4096) return;
    int ch = i >> 12;
    int r  = i & 4095;
    int co = r >> 5;
    int kk = r & 31;
    int tap   = ch >> 3;
    int ci256 = ((ch & 7) << 5) + kk;
    d_W1h[i] = __float2half(Wg1[co * 2304 + ci256 * 9 + tap]);
}

// ---------------- 1: 1x1 conv + L2 normalize --------------------------------
__global__ void __launch_bounds__(256)
embed_kernel(const float* __restrict__ in, const float* __restrict__ w, int which) {
    __shared__ float ws[64 * 64];
    int tid = threadIdx.x;
    for (int i = tid; i < 4096; i += 256) {
        int e = i >> 6, ci = i & 63;
        ws[ci * 64 + e] = w[i];
    }
    __syncthreads();
    int pix = blockIdx.x * 256 + tid;
    int b = pix >> 16, hw = pix & 65535;
    const float* ip = in + (b << 22) + hw;
    float acc[64];
#pragma unroll
    for (int e = 0; e < 64; e++) acc[e] = 0.f;
#pragma unroll 4
    for (int ci = 0; ci < 64; ci++) {
        float v = ip[ci << 16];
        const float4* wp = (const float4*)(ws + (ci << 6));
#pragma unroll
        for (int q = 0; q < 16; q++) {
            float4 w4 = wp[q];
            acc[4*q+0] = fmaf(w4.x, v, acc[4*q+0]);
            acc[4*q+1] = fmaf(w4.y, v, acc[4*q+1]);
            acc[4*q+2] = fmaf(w4.z, v, acc[4*q+2]);
            acc[4*q+3] = fmaf(w4.w, v, acc[4*q+3]);
        }
    }
    float ss = 0.f;
#pragma unroll
    for (int e = 0; e < 64; e++) ss = fmaf(acc[e], acc[e], ss);
    float inv = 1.f / (sqrtf(ss) + 1e-6f);
    float* op = (which ? d_yemb : d_xemb) + (b << 22) + hw;
#pragma unroll
    for (int e = 0; e < 64; e++) op[e << 16] = acc[e] * inv;
}

// ---------------- 2: r0 -----------------------------------------------------
__global__ void __launch_bounds__(256) r0_kernel() {
    int pix = blockIdx.x * 256 + threadIdx.x;
    int b = pix >> 16, hw = pix & 65535;
    const float* xp = d_xemb + (b << 22) + hw;
    const float* yp = d_yemb + (b << 22) + hw;
    float s = 0.f;
#pragma unroll 8
    for (int e = 0; e < 64; e++) s = fmaf(xp[e << 16], yp[e << 16], s);
    d_r0[pix] = (s + 1.f) * 0.5f;
}

// ---------------- 3: conv1 (3x3 256->128) fp16 mma, occupancy 2 -------------
// CTA 128co x 128px ; K=2304 in 72 chunks of 32. smem row stride 80B.
__global__ void __launch_bounds__(256, 2)
conv1_mma(const float* __restrict__ bn_g, const float* __restrict__ bn_b,
          const float* __restrict__ bn_m, const float* __restrict__ bn_v) {
    __shared__ __align__(16) char As[2][128 * RS];
    __shared__ __align__(16) char Bs[2][128 * RS];
    __shared__ float ssc[128], sbi[128];

    const int tid = threadIdx.x;
    const int lid = tid & 31;
    const int wid = tid >> 5;
    const int wm = wid >> 2;            // 0..1 (m block of 64)
    const int wn = wid & 3;             // 0..3 (n block of 32)
    const int b  = blockIdx.y;
    const int y  = blockIdx.x >> 1;
    const int x0 = (blockIdx.x & 1) << 7;
    const int col  = tid & 127;         // pixel for B fill
    const int half = tid >> 7;          // k-half for B fill

    if (tid < 128) {
        float iv = rsqrtf(bn_v[tid] + 1e-5f);
        float sc = bn_g[tid] * iv;
        ssc[tid] = sc;
        sbi[tid] = bn_b[tid] - bn_m[tid] * sc;
    }

    float acc[4][4][4];
#pragma unroll
    for (int i = 0; i < 4; i++)
#pragma unroll
        for (int j = 0; j < 4; j++)
#pragma unroll
            for (int c = 0; c < 4; c++) acc[i][j][c] = 0.f;

    float4 pa[2];
    float  pv[16];

    auto gload = [&](int ch) {
        const float4* asrc = (const float4*)(d_W1h + ch * 4096);
        pa[0] = asrc[tid];
        pa[1] = asrc[tid + 256];
        int tap = ch >> 3;
        int ci0 = (ch & 7) << 5;
        int grp = ci0 >> 6;
        int c0  = ci0 & 63;
        int dy = tap / 3 - 1, dx = tap % 3 - 1;
        int yy = y + dy;
        int xx = x0 + dx + col;
        bool inb = ((unsigned)yy < 256u) && ((unsigned)xx < 256u);
        long base = ((long)((b << 6) + c0 + (half << 4)) << 16) + yy * 256 + xx;
        const float* xp = d_xemb + base;
        const float* yp = d_yemb + base;
#pragma unroll
        for (int i = 0; i < 16; i++) {
            float vx = 0.f, vy = 0.f;
            if (grp != 1 && inb) vx = xp[i << 16];
            if (grp != 0 && inb) vy = yp[i << 16];
            float v;
            if      (grp == 0) v = vx;
            else if (grp == 1) v = vy;
            else if (grp == 2) v = fabsf(vx - vy);
            else               v = vx * vy;
            pv[i] = v;
        }
    };

    auto sstore = [&](int buf) {
        // A: float4 g covers (co = g>>2, 16B quarter = g&3)
        *(float4*)(As[buf] + (tid >> 2) * RS + (tid & 3) * 16) = pa[0];
        {
            int t1 = tid + 256;
            *(float4*)(As[buf] + (t1 >> 2) * RS + (t1 & 3) * 16) = pa[1];
        }
        char* bd = Bs[buf] + col * RS + half * 32;
#pragma unroll
        for (int j = 0; j < 8; j++)
            *(__half2*)(bd + j * 4) = __floats2half2_rn(pv[2 * j], pv[2 * j + 1]);
    };

    auto compute = [&](int buf) {
        uint32_t a_base = smem_u32(As[buf]) +
            (uint32_t)((wm * 64 + (lid & 15)) * RS + (lid >> 4) * 16);
        uint32_t b_base = smem_u32(Bs[buf]) +
            (uint32_t)((wn * 32 + (lid & 7) + ((lid >> 4) & 1) * 8) * RS +
                       ((lid >> 3) & 1) * 16);
#pragma unroll
        for (int st = 0; st < 2; st++) {
            uint32_t af[4][4], bf[2][4];
#pragma unroll
            for (int mt = 0; mt < 4; mt++)
                ldsm_x4(af[mt], a_base + mt * 16 * RS + st * 32);
#pragma unroll
            for (int bt = 0; bt < 2; bt++)
                ldsm_x4(bf[bt], b_base + bt * 16 * RS + st * 32);
#pragma unroll
            for (int mt = 0; mt < 4; mt++)
#pragma unroll
                for (int nt = 0; nt < 4; nt++) {
                    int bt = nt >> 1, pr = nt & 1;
                    mma_f16(acc[mt][nt], af[mt], bf[bt][pr * 2], bf[bt][pr * 2 + 1]);
                }
        }
    };

    gload(0);
    sstore(0);
    __syncthreads();
    for (int ch = 0; ch < 72; ch++) {
        int cur = ch & 1;
        if (ch < 71) gload(ch + 1);
        compute(cur);
        if (ch < 71) sstore(cur ^ 1);
        __syncthreads();
    }

    // epilogue: BN + ReLU
    int prow = y * 256 + x0 + wn * 32 + (lid & 3) * 2;
#pragma unroll
    for (int mt = 0; mt < 4; mt++) {
        int co0 = wm * 64 + mt * 16 + (lid >> 2);
        float sc0 = ssc[co0],     bi0 = sbi[co0];
        float sc1 = ssc[co0 + 8], bi1 = sbi[co0 + 8];
        float* hp0 = d_h + (((b << 7) + co0) << 16) + prow;
        float* hp1 = hp0 + (8 << 16);
#pragma unroll
        for (int nt = 0; nt < 4; nt++) {
            hp0[nt * 8]     = fmaxf(fmaf(acc[mt][nt][0], sc0, bi0), 0.f);
            hp0[nt * 8 + 1] = fmaxf(fmaf(acc[mt][nt][1], sc0, bi0), 0.f);
            hp1[nt * 8]     = fmaxf(fmaf(acc[mt][nt][2], sc1, bi1), 0.f);
            hp1[nt * 8 + 1] = fmaxf(fmaf(acc[mt][nt][3], sc1, bi1), 0.f);
        }
    }
}

// ---------------- 4: conv2 (3x3, 128->9) + bias + sigmoid, f32x2 ------------
__global__ void __launch_bounds__(256)
conv2_kernel(const float* __restrict__ Wg2, const float* __restrict__ bg2) {
    __shared__ float ht[8][324];
    __shared__ __align__(8) float ws2[720];   // [(cc*9+tap)][10] slots co0..8+pad
    int tid = threadIdx.x;
    int px = tid & 15, py = tid >> 4;
    int x0 = blockIdx.x * 16, y0 = blockIdx.y * 16;
    int x = x0 + px, y = y0 + py;
    int b = blockIdx.z;

    ull a01 = 0, a23 = 0, a45 = 0, a67 = 0, a89 = 0;

    for (int ci0 = 0; ci0 < 128; ci0 += 8) {
        __syncthreads();
        for (int i = tid; i < 2592; i += 256) {
            int ci = i / 324;
            int j  = i - ci * 324;
            int ry = j / 18;
            int rx = j - ry * 18;
            int gy = y0 + ry - 1, gx = x0 + rx - 1;
            float v = 0.f;
            if ((unsigned)gy < 256u && (unsigned)gx < 256u)
                v = d_h[(((b << 7) + ci0 + ci) << 16) + gy * 256 + gx];
            ht[ci][j] = v;
        }
        for (int i = tid; i < 720; i += 256) {
            int slot = i % 10, r = i / 10;
            int cc = r / 9, tap = r % 9;
            ws2[i] = (slot < 9) ? Wg2[slot * 1152 + (ci0 + cc) * 9 + tap] : 0.f;
        }
        __syncthreads();
#pragma unroll
        for (int cc = 0; cc < 8; cc++) {
#pragma unroll
            for (int tap = 0; tap < 9; tap++) {
                int dy = tap / 3, dx = tap % 3;
                float t = ht[cc][(py + dy) * 18 + px + dx];
                ull tp = pack2(t);
                const ull* wp = (const ull*)(ws2 + (cc * 9 + tap) * 10);
                a01 = ffma2(tp, wp[0], a01);
                a23 = ffma2(tp, wp[1], a23);
                a45 = ffma2(tp, wp[2], a45);
                a67 = ffma2(tp, wp[3], a67);
                a89 = ffma2(tp, wp[4], a89);
            }
        }
    }
    float acc[9];
    acc[0] = __uint_as_float((unsigned)a01); acc[1] = __uint_as_float((unsigned)(a01 >> 32));
    acc[2] = __uint_as_float((unsigned)a23); acc[3] = __uint_as_float((unsigned)(a23 >> 32));
    acc[4] = __uint_as_float((unsigned)a45); acc[5] = __uint_as_float((unsigned)(a45 >> 32));
    acc[6] = __uint_as_float((unsigned)a67); acc[7] = __uint_as_float((unsigned)(a67 >> 32));
    acc[8] = __uint_as_float((unsigned)a89);
#pragma unroll
    for (int co = 0; co < 9; co++) {
        float g = acc[co] + bg2[co];
        float s = 1.f / (1.f + __expf(-g));
        d_gates[((b * 9 + co) << 16) + y * 256 + x] = s;
    }
}

// ---------------- 5: gated propagation --------------------------------------
__global__ void __launch_bounds__(256) prop_kernel(float* __restrict__ outp, int which) {
    const int dys[9] = {-1, -1, 0, 1, 1,  1,  0, -1, 0};
    const int dxs[9] = { 0,  1, 1, 1, 0, -1, -1, -1, 0};
    int pix = blockIdx.x * 256 + threadIdx.x;
    int b = pix >> 16, hw = pix & 65535;
    int y = hw >> 8, x = hw & 255;
    const float* rin  = which ? d_r1 : d_r0;
    float*       rout = which ? outp : d_r1;

    float deg = 0.f, agg = 0.f;
#pragma unroll
    for (int d = 0; d < 9; d++) {
        float gv = d_gates[((b * 9 + d) << 16) + hw];
        deg += gv;
        int ny = y - dys[d];
        int nx = x - dxs[d];
        float nb = 0.f;
        if ((unsigned)ny < 256u && (unsigned)nx < 256u)
            nb = rin[(b << 16) + (ny << 8) + nx];
        agg = fmaf(gv, nb, agg);
    }
    float rn = 0.3f * rin[pix] + 0.7f * (agg / (deg + 1e-6f));
    if (which) rn = fminf(fmaxf(rn, 0.f), 1.f);
    rout[pix] = rn;
}

// ---------------- launch ----------------------------------------------------
extern "C" void kernel_launch(void* const* d_in, const int* in_sizes, int n_in,
                              void* d_out, int out_size) {
    const float* x        = (const float*)d_in[0];
    const float* y        = (const float*)d_in[1];
    const float* Wx       = (const float*)d_in[2];
    const float* Wy       = (const float*)d_in[3];
    const float* Wg1      = (const float*)d_in[4];
    const float* bn_gamma = (const float*)d_in[5];
    const float* bn_beta  = (const float*)d_in[6];
    const float* bn_mean  = (const float*)d_in[7];
    const float* bn_var   = (const float*)d_in[8];
    const float* Wg2      = (const float*)d_in[9];
    const float* bg2      = (const float*)d_in[10];
    float* out = (float*)d_out;

    prep_w1<<<(72 * 4096 + 255) / 256, 256>>>(Wg1);
    embed_kernel<<<2048, 256>>>(x, Wx, 0);
    embed_kernel<<<2048, 256>>>(y, Wy, 1);
    r0_kernel<<<2048, 256>>>();
    conv1_mma<<<dim3(512, BATCH), 256>>>(bn_gamma, bn_beta, bn_mean, bn_var);
    conv2_kernel<<<dim3(16, 16, BATCH), 256>>>(Wg2, bg2);
    prop_kernel<<<2048, 256>>>(out, 0);
    prop_kernel<<<2048, 256>>>(out, 1);
}

// round 16
// speedup vs baseline: 1.5426x; 1.5426x over previous
#include <cuda_runtime.h>
#include <math.h>
#include <cstdint>

typedef unsigned long long ull;

// ---------------- problem constants ----------------
#define BATCH 8
#define HWP   65536
#define G2    128
#define DD    9

// ---------------- scratch ----------------------------------------------------
__device__ __align__(16) float d_xemb[BATCH * 64 * HWP];
__device__ __align__(16) float d_yemb[BATCH * 64 * HWP];
__device__ __align__(16) float d_h   [BATCH * G2 * HWP];
__device__ __align__(16) float d_gates[BATCH * DD * HWP];
__device__ __align__(16) float d_r0  [BATCH * HWP];
__device__ __align__(16) float d_r1  [BATCH * HWP];
__device__ __align__(16) float d_WtA [144 * 2048];     // [chunk][co][kk] tf32 bits

// ---------------- helpers ----------------------------------------------------
__device__ __forceinline__ uint32_t smem_u32(const void* p) {
    uint32_t a;
    asm("{ .reg .u64 t; cvta.to.shared.u64 t, %1; cvt.u32.u64 %0, t; }" : "=r"(a) : "l"(p));
    return a;
}
__device__ __forceinline__ ull ffma2(ull a, ull b, ull c) {
    ull d; asm("fma.rn.f32x2 %0, %1, %2, %3;" : "=l"(d) : "l"(a), "l"(b), "l"(c)); return d;
}
__device__ __forceinline__ ull pack2(float a) {
    ull d; asm("mov.b64 %0, {%1, %1};" : "=l"(d) : "f"(a)); return d;
}
__device__ __forceinline__ uint32_t to_tf32(float f) {
    uint32_t u; asm("cvt.rna.tf32.f32 %0, %1;" : "=r"(u) : "f"(f)); return u;
}
__device__ __forceinline__ void ldsm_x4(uint32_t& r0, uint32_t& r1, uint32_t& r2, uint32_t& r3,
                                        uint32_t addr) {
    asm volatile("ldmatrix.sync.aligned.m8n8.x4.shared.b16 {%0,%1,%2,%3}, [%4];"
                 : "=r"(r0), "=r"(r1), "=r"(r2), "=r"(r3) : "r"(addr));
}
__device__ __forceinline__ void mma_tf32(float& d0, float& d1, float& d2, float& d3,
                                         uint32_t a0, uint32_t a1, uint32_t a2, uint32_t a3,
                                         uint32_t b0, uint32_t b1) {
    asm volatile("mma.sync.aligned.m16n8k8.row.col.f32.tf32.tf32.f32 "
                 "{%0,%1,%2,%3}, {%4,%5,%6,%7}, {%8,%9}, {%0,%1,%2,%3};"
                 : "+f"(d0), "+f"(d1), "+f"(d2), "+f"(d3)
                 : "r"(a0), "r"(a1), "r"(a2), "r"(a3), "r"(b0), "r"(b1));
}

// ---------------- 0: Wg1 -> tf32 tiles [ch][co][kk] -------------------------
// NEW k order: k = ch*16+kk ; tap = ch>>4 ; cw = ch&15 ;
// ci_l = kk>>2 ; grp = kk&3 ; gi channel = grp*64 + cw*4 + ci_l
__global__ void prep_w_tc(const float* __restrict__ Wg1) {
    int i = blockIdx.x * 256 + threadIdx.x;
    if (i >= 144 * 2048) return;
    int ch = i >> 11;
    int r  = i & 2047;
    int co = r >> 4;
    int kk = r & 15;
    int tap  = ch >> 4;
    int cw   = ch & 15;
    int ci_l = kk >> 2;
    int grp  = kk & 3;
    int ci256 = grp * 64 + cw * 4 + ci_l;
    float w = Wg1[co * 2304 + ci256 * 9 + tap];
    ((uint32_t*)d_WtA)[i] = to_tf32(w);
}

// ---------------- 1: 1x1 conv + L2 normalize --------------------------------
__global__ void __launch_bounds__(256)
embed_kernel(const float* __restrict__ in, const float* __restrict__ w, int which) {
    __shared__ float ws[64 * 64];
    int tid = threadIdx.x;
    for (int i = tid; i < 4096; i += 256) {
        int e = i >> 6, ci = i & 63;
        ws[ci * 64 + e] = w[i];
    }
    __syncthreads();
    int pix = blockIdx.x * 256 + tid;
    int b = pix >> 16, hw = pix & 65535;
    const float* ip = in + (b << 22) + hw;
    float acc[64];
#pragma unroll
    for (int e = 0; e < 64; e++) acc[e] = 0.f;
#pragma unroll 4
    for (int ci = 0; ci < 64; ci++) {
        float v = ip[ci << 16];
        const float4* wp = (const float4*)(ws + (ci << 6));
#pragma unroll
        for (int q = 0; q < 16; q++) {
            float4 w4 = wp[q];
            acc[4*q+0] = fmaf(w4.x, v, acc[4*q+0]);
            acc[4*q+1] = fmaf(w4.y, v, acc[4*q+1]);
            acc[4*q+2] = fmaf(w4.z, v, acc[4*q+2]);
            acc[4*q+3] = fmaf(w4.w, v, acc[4*q+3]);
        }
    }
    float ss = 0.f;
#pragma unroll
    for (int e = 0; e < 64; e++) ss = fmaf(acc[e], acc[e], ss);
    float inv = 1.f / (sqrtf(ss) + 1e-6f);
    float* op = (which ? d_yemb : d_xemb) + (b << 22) + hw;
#pragma unroll
    for (int e = 0; e < 64; e++) op[e << 16] = acc[e] * inv;
}

// ---------------- 2: r0 -----------------------------------------------------
__global__ void __launch_bounds__(256) r0_kernel() {
    int pix = blockIdx.x * 256 + threadIdx.x;
    int b = pix >> 16, hw = pix & 65535;
    const float* xp = d_xemb + (b << 22) + hw;
    const float* yp = d_yemb + (b << 22) + hw;
    float s = 0.f;
#pragma unroll 8
    for (int e = 0; e < 64; e++) s = fmaf(xp[e << 16], yp[e << 16], s);
    d_r0[pix] = (s + 1.f) * 0.5f;
}

// ---------------- 3: conv1 via mma.sync tf32 implicit GEMM ------------------
// CTA: 128 co x 128 px, K=2304 in 144 chunks of 16 = (tap, 4ch) x 4 groups.
// Each thread loads 4 emb floats, synthesizes 8 B entries (2 aligned uint4).
__global__ void __launch_bounds__(256, 2)
conv1_mma(const float* __restrict__ bn_g, const float* __restrict__ bn_b,
          const float* __restrict__ bn_m, const float* __restrict__ bn_v) {
    __shared__ __align__(16) float As[2][2560];   // 128 rows * 20
    __shared__ __align__(16) float Bs[2][2560];
    __shared__ float ssc[128], sbi[128];

    const int tid = threadIdx.x;
    const int lid = tid & 31;
    const int wid = tid >> 5;
    const int wm = wid >> 2;            // 0..1  (m block of 64)
    const int wn = wid & 3;             // 0..3  (n block of 32)
    const int b  = blockIdx.y;
    const int y  = blockIdx.x >> 1;
    const int x0 = (blockIdx.x & 1) << 7;
    const int col  = tid & 127;         // pixel for B fill
    const int half = tid >> 7;          // ci-pair selector

    if (tid < 128) {
        float iv = rsqrtf(bn_v[tid] + 1e-5f);
        float sc = bn_g[tid] * iv;
        ssc[tid] = sc;
        sbi[tid] = bn_b[tid] - bn_m[tid] * sc;
    }

    float acc[4][4][4];
#pragma unroll
    for (int i = 0; i < 4; i++)
#pragma unroll
        for (int j = 0; j < 4; j++)
#pragma unroll
            for (int c = 0; c < 4; c++) acc[i][j][c] = 0.f;

    // prefetch registers
    float4 pa[2];
    float  pvx[2], pvy[2];

    auto gload = [&](int ch) {
        const float4* asrc = (const float4*)(d_WtA + ch * 2048);
        pa[0] = asrc[tid];
        pa[1] = asrc[tid + 256];
        int tap = ch >> 4;
        int cw  = ch & 15;
        int dy = tap / 3 - 1, dx = tap % 3 - 1;
        int yy = y + dy;
        int xx = x0 + dx + col;
        bool inb = ((unsigned)yy < 256u) && ((unsigned)xx < 256u);
        int c0 = cw * 4 + half * 2;               // emb channel base (0..62)
        int base = (((b << 6) + c0) << 16) + yy * 256 + xx;
        pvx[0] = inb ? d_xemb[base]       : 0.f;
        pvy[0] = inb ? d_yemb[base]       : 0.f;
        pvx[1] = inb ? d_xemb[base + HWP] : 0.f;
        pvy[1] = inb ? d_yemb[base + HWP] : 0.f;
    };

    auto sstore = [&](int buf) {
        // A: 512 float4; thread t covers (co = t>>2, k4 = t&3)
        {
            int t0 = tid;
            ((float4*)(As[buf] + (t0 >> 2) * 20 + (t0 & 3) * 4))[0] = pa[0];
            int t1 = tid + 256;
            ((float4*)(As[buf] + (t1 >> 2) * 20 + (t1 & 3) * 4))[0] = pa[1];
        }
        // B: per thread, 2 channels -> 2 x uint4 {x, y, |x-y|, x*y}
#pragma unroll
        for (int c = 0; c < 2; c++) {
            float vx = pvx[c], vy = pvy[c];
            uint4 v;
            v.x = to_tf32(vx);
            v.y = to_tf32(vy);
            v.z = to_tf32(fabsf(vx - vy));
            v.w = to_tf32(vx * vy);
            int ci_l = half * 2 + c;              // 0..3
            *(uint4*)(Bs[buf] + col * 20 + ci_l * 4) = v;
        }
    };

    auto compute = [&](int buf) {
        uint32_t As_b = smem_u32(As[buf]);
        uint32_t Bs_b = smem_u32(Bs[buf]);
        uint32_t a_base = As_b + (uint32_t)((wm * 64 + (lid & 7) + ((lid >> 3) & 1) * 8) * 80
                                            + ((lid >> 4) & 1) * 16);
        uint32_t b_base = Bs_b + (uint32_t)((wn * 32 + (lid & 7) + ((lid >> 4) & 1) * 8) * 80
                                            + ((lid >> 3) & 1) * 16);
#pragma unroll
        for (int k8 = 0; k8 < 2; k8++) {
            uint32_t af[4][4], bf[2][4];
#pragma unroll
            for (int mt = 0; mt < 4; mt++)
                ldsm_x4(af[mt][0], af[mt][1], af[mt][2], af[mt][3],
                        a_base + k8 * 32 + mt * 1280);
#pragma unroll
            for (int bt = 0; bt < 2; bt++)
                ldsm_x4(bf[bt][0], bf[bt][1], bf[bt][2], bf[bt][3],
                        b_base + k8 * 32 + bt * 1280);
#pragma unroll
            for (int mt = 0; mt < 4; mt++)
#pragma unroll
                for (int nt = 0; nt < 4; nt++) {
                    int bt = nt >> 1, pr = nt & 1;
                    mma_tf32(acc[mt][nt][0], acc[mt][nt][1], acc[mt][nt][2], acc[mt][nt][3],
                             af[mt][0], af[mt][1], af[mt][2], af[mt][3],
                             bf[bt][pr * 2], bf[bt][pr * 2 + 1]);
                }
        }
    };

    gload(0);
    sstore(0);
    __syncthreads();
    for (int ch = 0; ch < 144; ch++) {
        int cur = ch & 1;
        if (ch < 143) gload(ch + 1);
        compute(cur);
        if (ch < 143) sstore(cur ^ 1);
        __syncthreads();
    }

    // epilogue: BN + ReLU, direct fragment stores (2 consecutive floats/lane)
    int prow = y * 256 + x0 + wn * 32 + (lid & 3) * 2;
#pragma unroll
    for (int mt = 0; mt < 4; mt++) {
        int co0 = wm * 64 + mt * 16 + (lid >> 2);
        float sc0 = ssc[co0],     bi0 = sbi[co0];
        float sc1 = ssc[co0 + 8], bi1 = sbi[co0 + 8];
        float* hp0 = d_h + (((b << 7) + co0) << 16) + prow;
        float* hp1 = hp0 + (8 << 16);
#pragma unroll
        for (int nt = 0; nt < 4; nt++) {
            hp0[nt * 8]     = fmaxf(fmaf(acc[mt][nt][0], sc0, bi0), 0.f);
            hp0[nt * 8 + 1] = fmaxf(fmaf(acc[mt][nt][1], sc0, bi0), 0.f);
            hp1[nt * 8]     = fmaxf(fmaf(acc[mt][nt][2], sc1, bi1), 0.f);
            hp1[nt * 8 + 1] = fmaxf(fmaf(acc[mt][nt][3], sc1, bi1), 0.f);
        }
    }
}

// ---------------- 4: conv2 (3x3, 128->9) + bias + sigmoid, f32x2 ------------
__global__ void __launch_bounds__(256)
conv2_kernel(const float* __restrict__ Wg2, const float* __restrict__ bg2) {
    __shared__ float ht[8][324];
    __shared__ __align__(8) float ws2[720];   // [(cc*9+tap)][10] slots co0..8+pad
    int tid = threadIdx.x;
    int px = tid & 15, py = tid >> 4;
    int x0 = blockIdx.x * 16, y0 = blockIdx.y * 16;
    int x = x0 + px, y = y0 + py;
    int b = blockIdx.z;

    ull a01 = 0, a23 = 0, a45 = 0, a67 = 0, a89 = 0;

    for (int ci0 = 0; ci0 < 128; ci0 += 8) {
        __syncthreads();
        for (int i = tid; i < 2592; i += 256) {
            int ci = i / 324;
            int j  = i - ci * 324;
            int ry = j / 18;
            int rx = j - ry * 18;
            int gy = y0 + ry - 1, gx = x0 + rx - 1;
            float v = 0.f;
            if ((unsigned)gy < 256u && (unsigned)gx < 256u)
                v = d_h[(((b << 7) + ci0 + ci) << 16) + gy * 256 + gx];
            ht[ci][j] = v;
        }
        for (int i = tid; i < 720; i += 256) {
            int slot = i % 10, r = i / 10;
            int cc = r / 9, tap = r % 9;
            ws2[i] = (slot < 9) ? Wg2[slot * 1152 + (ci0 + cc) * 9 + tap] : 0.f;
        }
        __syncthreads();
#pragma unroll
        for (int cc = 0; cc < 8; cc++) {
#pragma unroll
            for (int tap = 0; tap < 9; tap++) {
                int dy = tap / 3, dx = tap % 3;
                float t = ht[cc][(py + dy) * 18 + px + dx];
                ull tp = pack2(t);
                const ull* wp = (const ull*)(ws2 + (cc * 9 + tap) * 10);
                a01 = ffma2(tp, wp[0], a01);
                a23 = ffma2(tp, wp[1], a23);
                a45 = ffma2(tp, wp[2], a45);
                a67 = ffma2(tp, wp[3], a67);
                a89 = ffma2(tp, wp[4], a89);
            }
        }
    }
    float acc[9];
    acc[0] = __uint_as_float((unsigned)a01); acc[1] = __uint_as_float((unsigned)(a01 >> 32));
    acc[2] = __uint_as_float((unsigned)a23); acc[3] = __uint_as_float((unsigned)(a23 >> 32));
    acc[4] = __uint_as_float((unsigned)a45); acc[5] = __uint_as_float((unsigned)(a45 >> 32));
    acc[6] = __uint_as_float((unsigned)a67); acc[7] = __uint_as_float((unsigned)(a67 >> 32));
    acc[8] = __uint_as_float((unsigned)a89);
#pragma unroll
    for (int co = 0; co < 9; co++) {
        float g = acc[co] + bg2[co];
        float s = 1.f / (1.f + __expf(-g));
        d_gates[((b * 9 + co) << 16) + y * 256 + x] = s;
    }
}

// ---------------- 5: gated propagation --------------------------------------
__global__ void __launch_bounds__(256) prop_kernel(float* __restrict__ outp, int which) {
    const int dys[9] = {-1, -1, 0, 1, 1,  1,  0, -1, 0};
    const int dxs[9] = { 0,  1, 1, 1, 0, -1, -1, -1, 0};
    int pix = blockIdx.x * 256 + threadIdx.x;
    int b = pix >> 16, hw = pix & 65535;
    int y = hw >> 8, x = hw & 255;
    const float* rin  = which ? d_r1 : d_r0;
    float*       rout = which ? outp : d_r1;

    float deg = 0.f, agg = 0.f;
#pragma unroll
    for (int d = 0; d < 9; d++) {
        float gv = d_gates[((b * 9 + d) << 16) + hw];
        deg += gv;
        int ny = y - dys[d];
        int nx = x - dxs[d];
        float nb = 0.f;
        if ((unsigned)ny < 256u && (unsigned)nx < 256u)
            nb = rin[(b << 16) + (ny << 8) + nx];
        agg = fmaf(gv, nb, agg);
    }
    float rn = 0.3f * rin[pix] + 0.7f * (agg / (deg + 1e-6f));
    if (which) rn = fminf(fmaxf(rn, 0.f), 1.f);
    rout[pix] = rn;
}

// ---------------- launch ----------------------------------------------------
extern "C" void kernel_launch(void* const* d_in, const int* in_sizes, int n_in,
                              void* d_out, int out_size) {
    const float* x        = (const float*)d_in[0];
    const float* y        = (const float*)d_in[1];
    const float* Wx       = (const float*)d_in[2];
    const float* Wy       = (const float*)d_in[3];
    const float* Wg1      = (const float*)d_in[4];
    const float* bn_gamma = (const float*)d_in[5];
    const float* bn_beta  = (const float*)d_in[6];
    const float* bn_mean  = (const float*)d_in[7];
    const float* bn_var   = (const float*)d_in[8];
    const float* Wg2      = (const float*)d_in[9];
    const float* bg2      = (const float*)d_in[10];
    float* out = (float*)d_out;

    prep_w_tc<<<(144 * 2048 + 255) / 256, 256>>>(Wg1);
    embed_kernel<<<2048, 256>>>(x, Wx, 0);
    embed_kernel<<<2048, 256>>>(y, Wy, 1);
    r0_kernel<<<2048, 256>>>();
    conv1_mma<<<dim3(512, BATCH), 256>>>(bn_gamma, bn_beta, bn_mean, bn_var);
    conv2_kernel<<<dim3(16, 16, BATCH), 256>>>(Wg2, bg2);
    prop_kernel<<<2048, 256>>>(out, 0);
    prop_kernel<<<2048, 256>>>(out, 1);
}

// round 17
// speedup vs baseline: 2.1138x; 1.3703x over previous
#include <cuda_runtime.h>
#include <cuda_fp16.h>
#include <math.h>
#include <cstdint>

typedef unsigned long long ull;

// ---------------- problem constants ----------------
#define BATCH 8
#define HWP   65536
#define G2    128
#define DD    9

// smem row stride in bytes (multiple of 16 for ldmatrix/float4)
#define RS 80

// ---------------- scratch ----------------------------------------------------
__device__ __align__(16) float d_xemb[BATCH * 64 * HWP];
__device__ __align__(16) float d_yemb[BATCH * 64 * HWP];
__device__ __align__(16) float d_h   [BATCH * G2 * HWP];
__device__ __align__(16) float d_gates[BATCH * DD * HWP];
__device__ __align__(16) float d_r0  [BATCH * HWP];
__device__ __align__(16) float d_r1  [BATCH * HWP];
__device__ __align__(16) __half d_W1h[72 * 4096];   // [ch][co][kk] fp16, new K order

// ---------------- helpers ----------------------------------------------------
__device__ __forceinline__ uint32_t smem_u32(const void* p) {
    uint32_t a;
    asm("{ .reg .u64 t; cvta.to.shared.u64 t, %1; cvt.u32.u64 %0, t; }" : "=r"(a) : "l"(p));
    return a;
}
__device__ __forceinline__ ull ffma2(ull a, ull b, ull c) {
    ull d; asm("fma.rn.f32x2 %0, %1, %2, %3;" : "=l"(d) : "l"(a), "l"(b), "l"(c)); return d;
}
__device__ __forceinline__ ull pack2(float a) {
    ull d; asm("mov.b64 %0, {%1, %1};" : "=l"(d) : "f"(a)); return d;
}
__device__ __forceinline__ void ldsm_x4(uint32_t* r, uint32_t addr) {
    asm volatile("ldmatrix.sync.aligned.m8n8.x4.shared.b16 {%0,%1,%2,%3}, [%4];"
                 : "=r"(r[0]), "=r"(r[1]), "=r"(r[2]), "=r"(r[3]) : "r"(addr));
}
__device__ __forceinline__ void mma_f16(float* d,
                                        const uint32_t* a, uint32_t b0, uint32_t b1) {
    asm volatile("mma.sync.aligned.m16n8k16.row.col.f32.f16.f16.f32 "
                 "{%0,%1,%2,%3}, {%4,%5,%6,%7}, {%8,%9}, {%0,%1,%2,%3};"
                 : "+f"(d[0]), "+f"(d[1]), "+f"(d[2]), "+f"(d[3])
                 : "r"(a[0]), "r"(a[1]), "r"(a[2]), "r"(a[3]), "r"(b0), "r"(b1));
}

// ---------------- 0: Wg1 -> fp16 tiles [ch][co][kk], interleaved K ----------
// k = ch*32+kk ; tap = ch>>3 ; cw = ch&7 ; ci_l = kk>>2 ; grp = kk&3 ;
// gi channel = grp*64 + cw*8 + ci_l
__global__ void prep_w1(const float* __restrict__ Wg1) {
    int i = blockIdx.x * 256 + threadIdx.x;
    if (i >= 72 * 4096) return;
    int ch = i >> 12;
    int r  = i & 4095;
    int co = r >> 5;
    int kk = r & 31;
    int tap  = ch >> 3;
    int cw   = ch & 7;
    int ci_l = kk >> 2;
    int grp  = kk & 3;
    int ci256 = grp * 64 + cw * 8 + ci_l;
    d_W1h[i] = __float2half(Wg1[co * 2304 + ci256 * 9 + tap]);
}

// ---------------- 1: 1x1 conv + L2 normalize --------------------------------
__global__ void __launch_bounds__(256)
embed_kernel(const float* __restrict__ in, const float* __restrict__ w, int which) {
    __shared__ float ws[64 * 64];
    int tid = threadIdx.x;
    for (int i = tid; i < 4096; i += 256) {
        int e = i >> 6, ci = i & 63;
        ws[ci * 64 + e] = w[i];
    }
    __syncthreads();
    int pix = blockIdx.x * 256 + tid;
    int b = pix >> 16, hw = pix & 65535;
    const float* ip = in + (b << 22) + hw;
    float acc[64];
#pragma unroll
    for (int e = 0; e < 64; e++) acc[e] = 0.f;
#pragma unroll 4
    for (int ci = 0; ci < 64; ci++) {
        float v = ip[ci << 16];
        const float4* wp = (const float4*)(ws + (ci << 6));
#pragma unroll
        for (int q = 0; q < 16; q++) {
            float4 w4 = wp[q];
            acc[4*q+0] = fmaf(w4.x, v, acc[4*q+0]);
            acc[4*q+1] = fmaf(w4.y, v, acc[4*q+1]);
            acc[4*q+2] = fmaf(w4.z, v, acc[4*q+2]);
            acc[4*q+3] = fmaf(w4.w, v, acc[4*q+3]);
        }
    }
    float ss = 0.f;
#pragma unroll
    for (int e = 0; e < 64; e++) ss = fmaf(acc[e], acc[e], ss);
    float inv = 1.f / (sqrtf(ss) + 1e-6f);
    float* op = (which ? d_yemb : d_xemb) + (b << 22) + hw;
#pragma unroll
    for (int e = 0; e < 64; e++) op[e << 16] = acc[e] * inv;
}

// ---------------- 2: r0 -----------------------------------------------------
__global__ void __launch_bounds__(256) r0_kernel() {
    int pix = blockIdx.x * 256 + threadIdx.x;
    int b = pix >> 16, hw = pix & 65535;
    const float* xp = d_xemb + (b << 22) + hw;
    const float* yp = d_yemb + (b << 22) + hw;
    float s = 0.f;
#pragma unroll 8
    for (int e = 0; e < 64; e++) s = fmaf(xp[e << 16], yp[e << 16], s);
    d_r0[pix] = (s + 1.f) * 0.5f;
}

// ---------------- 3: conv1 (3x3 256->128) fp16 mma, light gload, occ 2 ------
// CTA 128co x 128px ; K=2304 in 72 chunks of 32 = (tap, 8ch) x 4 groups.
// Each thread loads 8 emb floats, synthesizes 16 fp16 B entries (4 x uint2).
__global__ void __launch_bounds__(256, 2)
conv1_mma(const float* __restrict__ bn_g, const float* __restrict__ bn_b,
          const float* __restrict__ bn_m, const float* __restrict__ bn_v) {
    __shared__ __align__(16) char As[2][128 * RS];
    __shared__ __align__(16) char Bs[2][128 * RS];
    __shared__ float ssc[128], sbi[128];

    const int tid = threadIdx.x;
    const int lid = tid & 31;
    const int wid = tid >> 5;
    const int wm = wid >> 2;            // 0..1 (m block of 64)
    const int wn = wid & 3;             // 0..3 (n block of 32)
    const int b  = blockIdx.y;
    const int y  = blockIdx.x >> 1;
    const int x0 = (blockIdx.x & 1) << 7;
    const int col  = tid & 127;         // pixel for B fill
    const int half = tid >> 7;          // channel-quad selector

    if (tid < 128) {
        float iv = rsqrtf(bn_v[tid] + 1e-5f);
        float sc = bn_g[tid] * iv;
        ssc[tid] = sc;
        sbi[tid] = bn_b[tid] - bn_m[tid] * sc;
    }

    float acc[4][4][4];
#pragma unroll
    for (int i = 0; i < 4; i++)
#pragma unroll
        for (int j = 0; j < 4; j++)
#pragma unroll
            for (int c = 0; c < 4; c++) acc[i][j][c] = 0.f;

    float4 pa[2];
    float  pvx[4], pvy[4];

    auto gload = [&](int ch) {
        const float4* asrc = (const float4*)(d_W1h + ch * 4096);
        pa[0] = asrc[tid];
        pa[1] = asrc[tid + 256];
        int tap = ch >> 3;
        int cw  = ch & 7;
        int dy = tap / 3 - 1, dx = tap % 3 - 1;
        int yy = y + dy;
        int xx = x0 + dx + col;
        bool inb = ((unsigned)yy < 256u) && ((unsigned)xx < 256u);
        int c0 = cw * 8 + half * 4;               // emb channel base (0..60)
        int base = (((b << 6) + c0) << 16) + yy * 256 + xx;
#pragma unroll
        for (int c = 0; c < 4; c++) {
            pvx[c] = inb ? d_xemb[base + c * HWP] : 0.f;
            pvy[c] = inb ? d_yemb[base + c * HWP] : 0.f;
        }
    };

    auto sstore = [&](int buf) {
        // A: float4 g covers (co = g>>2, 16B quarter = g&3)
        *(float4*)(As[buf] + (tid >> 2) * RS + (tid & 3) * 16) = pa[0];
        {
            int t1 = tid + 256;
            *(float4*)(As[buf] + (t1 >> 2) * RS + (t1 & 3) * 16) = pa[1];
        }
        // B: per channel -> 4 halves {x, y, |x-y|, x*y} = one uint2
#pragma unroll
        for (int c = 0; c < 4; c++) {
            float vx = pvx[c], vy = pvy[c];
            __half2 h01 = __floats2half2_rn(vx, vy);
            __half2 h23 = __floats2half2_rn(fabsf(vx - vy), vx * vy);
            uint2 v;
            v.x = *(uint32_t*)&h01;
            v.y = *(uint32_t*)&h23;
            int ci_l = half * 4 + c;              // 0..7
            *(uint2*)(Bs[buf] + col * RS + ci_l * 8) = v;
        }
    };

    auto compute = [&](int buf) {
        uint32_t a_base = smem_u32(As[buf]) +
            (uint32_t)((wm * 64 + (lid & 15)) * RS + (lid >> 4) * 16);
        uint32_t b_base = smem_u32(Bs[buf]) +
            (uint32_t)((wn * 32 + (lid & 7) + ((lid >> 4) & 1) * 8) * RS +
                       ((lid >> 3) & 1) * 16);
#pragma unroll
        for (int st = 0; st < 2; st++) {
            uint32_t af[4][4], bf[2][4];
#pragma unroll
            for (int mt = 0; mt < 4; mt++)
                ldsm_x4(af[mt], a_base + mt * 16 * RS + st * 32);
#pragma unroll
            for (int bt = 0; bt < 2; bt++)
                ldsm_x4(bf[bt], b_base + bt * 16 * RS + st * 32);
#pragma unroll
            for (int mt = 0; mt < 4; mt++)
#pragma unroll
                for (int nt = 0; nt < 4; nt++) {
                    int bt = nt >> 1, pr = nt & 1;
                    mma_f16(acc[mt][nt], af[mt], bf[bt][pr * 2], bf[bt][pr * 2 + 1]);
                }
        }
    };

    gload(0);
    sstore(0);
    __syncthreads();
    for (int ch = 0; ch < 72; ch++) {
        int cur = ch & 1;
        if (ch < 71) gload(ch + 1);
        compute(cur);
        if (ch < 71) sstore(cur ^ 1);
        __syncthreads();
    }

    // epilogue: BN + ReLU
    int prow = y * 256 + x0 + wn * 32 + (lid & 3) * 2;
#pragma unroll
    for (int mt = 0; mt < 4; mt++) {
        int co0 = wm * 64 + mt * 16 + (lid >> 2);
        float sc0 = ssc[co0],     bi0 = sbi[co0];
        float sc1 = ssc[co0 + 8], bi1 = sbi[co0 + 8];
        float* hp0 = d_h + (((b << 7) + co0) << 16) + prow;
        float* hp1 = hp0 + (8 << 16);
#pragma unroll
        for (int nt = 0; nt < 4; nt++) {
            hp0[nt * 8]     = fmaxf(fmaf(acc[mt][nt][0], sc0, bi0), 0.f);
            hp0[nt * 8 + 1] = fmaxf(fmaf(acc[mt][nt][1], sc0, bi0), 0.f);
            hp1[nt * 8]     = fmaxf(fmaf(acc[mt][nt][2], sc1, bi1), 0.f);
            hp1[nt * 8 + 1] = fmaxf(fmaf(acc[mt][nt][3], sc1, bi1), 0.f);
        }
    }
}

// ---------------- 4: conv2 (3x3, 128->9) + bias + sigmoid, f32x2 ------------
__global__ void __launch_bounds__(256)
conv2_kernel(const float* __restrict__ Wg2, const float* __restrict__ bg2) {
    __shared__ float ht[8][324];
    __shared__ __align__(8) float ws2[720];   // [(cc*9+tap)][10] slots co0..8+pad
    int tid = threadIdx.x;
    int px = tid & 15, py = tid >> 4;
    int x0 = blockIdx.x * 16, y0 = blockIdx.y * 16;
    int x = x0 + px, y = y0 + py;
    int b = blockIdx.z;

    ull a01 = 0, a23 = 0, a45 = 0, a67 = 0, a89 = 0;

    for (int ci0 = 0; ci0 < 128; ci0 += 8) {
        __syncthreads();
        for (int i = tid; i < 2592; i += 256) {
            int ci = i / 324;
            int j  = i - ci * 324;
            int ry = j / 18;
            int rx = j - ry * 18;
            int gy = y0 + ry - 1, gx = x0 + rx - 1;
            float v = 0.f;
            if ((unsigned)gy < 256u && (unsigned)gx < 256u)
                v = d_h[(((b << 7) + ci0 + ci) << 16) + gy * 256 + gx];
            ht[ci][j] = v;
        }
        for (int i = tid; i < 720; i += 256) {
            int slot = i % 10, r = i / 10;
            int cc = r / 9, tap = r % 9;
            ws2[i] = (slot < 9) ? Wg2[slot * 1152 + (ci0 + cc) * 9 + tap] : 0.f;
        }
        __syncthreads();
#pragma unroll
        for (int cc = 0; cc < 8; cc++) {
#pragma unroll
            for (int tap = 0; tap < 9; tap++) {
                int dy = tap / 3, dx = tap % 3;
                float t = ht[cc][(py + dy) * 18 + px + dx];
                ull tp = pack2(t);
                const ull* wp = (const ull*)(ws2 + (cc * 9 + tap) * 10);
                a01 = ffma2(tp, wp[0], a01);
                a23 = ffma2(tp, wp[1], a23);
                a45 = ffma2(tp, wp[2], a45);
                a67 = ffma2(tp, wp[3], a67);
                a89 = ffma2(tp, wp[4], a89);
            }
        }
    }
    float acc[9];
    acc[0] = __uint_as_float((unsigned)a01); acc[1] = __uint_as_float((unsigned)(a01 >> 32));
    acc[2] = __uint_as_float((unsigned)a23); acc[3] = __uint_as_float((unsigned)(a23 >> 32));
    acc[4] = __uint_as_float((unsigned)a45); acc[5] = __uint_as_float((unsigned)(a45 >> 32));
    acc[6] = __uint_as_float((unsigned)a67); acc[7] = __uint_as_float((unsigned)(a67 >> 32));
    acc[8] = __uint_as_float((unsigned)a89);
#pragma unroll
    for (int co = 0; co < 9; co++) {
        float g = acc[co] + bg2[co];
        float s = 1.f / (1.f + __expf(-g));
        d_gates[((b * 9 + co) << 16) + y * 256 + x] = s;
    }
}

// ---------------- 5: gated propagation --------------------------------------
__global__ void __launch_bounds__(256) prop_kernel(float* __restrict__ outp, int which) {
    const int dys[9] = {-1, -1, 0, 1, 1,  1,  0, -1, 0};
    const int dxs[9] = { 0,  1, 1, 1, 0, -1, -1, -1, 0};
    int pix = blockIdx.x * 256 + threadIdx.x;
    int b = pix >> 16, hw = pix & 65535;
    int y = hw >> 8, x = hw & 255;
    const float* rin  = which ? d_r1 : d_r0;
    float*       rout = which ? outp : d_r1;

    float deg = 0.f, agg = 0.f;
#pragma unroll
    for (int d = 0; d < 9; d++) {
        float gv = d_gates[((b * 9 + d) << 16) + hw];
        deg += gv;
        int ny = y - dys[d];
        int nx = x - dxs[d];
        float nb = 0.f;
        if ((unsigned)ny < 256u && (unsigned)nx < 256u)
            nb = rin[(b << 16) + (ny << 8) + nx];
        agg = fmaf(gv, nb, agg);
    }
    float rn = 0.3f * rin[pix] + 0.7f * (agg / (deg + 1e-6f));
    if (which) rn = fminf(fmaxf(rn, 0.f), 1.f);
    rout[pix] = rn;
}

// ---------------- launch ----------------------------------------------------
extern "C" void kernel_launch(void* const* d_in, const int* in_sizes, int n_in,
                              void* d_out, int out_size) {
    const float* x        = (const float*)d_in[0];
    const float* y        = (const float*)d_in[1];
    const float* Wx       = (const float*)d_in[2];
    const float* Wy       = (const float*)d_in[3];
    const float* Wg1      = (const float*)d_in[4];
    const float* bn_gamma = (const float*)d_in[5];
    const float* bn_beta  = (const float*)d_in[6];
    const float* bn_mean  = (const float*)d_in[7];
    const float* bn_var   = (const float*)d_in[8];
    const float* Wg2      = (const float*)d_in[9];
    const float* bg2      = (const float*)d_in[10];
    float* out = (float*)d_out;

    prep_w1<<<(72 * 4096 + 255) / 256, 256>>>(Wg1);
    embed_kernel<<<2048, 256>>>(x, Wx, 0);
    embed_kernel<<<2048, 256>>>(y, Wy, 1);
    r0_kernel<<<2048, 256>>>();
    conv1_mma<<<dim3(512, BATCH), 256>>>(bn_gamma, bn_beta, bn_mean, bn_var);
    conv2_kernel<<<dim3(16, 16, BATCH), 256>>>(Wg2, bg2);
    prop_kernel<<<2048, 256>>>(out, 0);
    prop_kernel<<<2048, 256>>>(out, 1);
}